// round 11
// baseline (speedup 1.0000x reference)
#include <cuda_runtime.h>
#include <math.h>

#define BB 8
#define CC 256
#define NN 2048
#define HH 32
#define LDW 136
#define NT 32     // j-iterations: NT * 64 == NN

// Scratch (__device__ globals; no allocation in kernel_launch)
__device__ float g_q [BB * NN * HH];            // q[b,n,h]   (tf32-rounded)
__device__ float g_kT[BB * NN * HH];            // k^T[b,n,h] (tf32-rounded)
__device__ float g_v [BB * CC * NN];            // v[b,c,n]   (tf32-rounded)

// fused-kernel smem layout (float offsets) — V full-tile double buffer
#define OFF_Q    0                         // 128 x 36 (tf32)
#define OFF_KT   (128*36)                  // 2 x 64 x 36
#define OFF_P    (OFF_KT + 2*64*36)        // 128 x 68
#define OFF_V    (OFF_P + 128*68)          // 2 x 256 x 68   (full 64-j tiles)
#define OFF_RS   (OFF_V + 2*256*68)        // 128 x 4
#define OFF_INV  (OFF_RS + 128*4)          // 128
#define SMEM_FLOATS (OFF_INV + 128)
#define SMEM_BYTES  (SMEM_FLOATS * 4)      // 213,504 B

__device__ __forceinline__ unsigned f2tf32(float f) {
    unsigned u;
    asm("cvt.rna.tf32.f32 %0, %1;" : "=r"(u) : "f"(f));
    return u;
}

__device__ __forceinline__ void mma_tf32(float c[4],
    unsigned a0, unsigned a1, unsigned a2, unsigned a3,
    unsigned b0, unsigned b1)
{
    asm volatile(
        "mma.sync.aligned.m16n8k8.row.col.f32.tf32.tf32.f32 "
        "{%0,%1,%2,%3}, {%4,%5,%6,%7}, {%8,%9}, {%0,%1,%2,%3};"
        : "+f"(c[0]), "+f"(c[1]), "+f"(c[2]), "+f"(c[3])
        : "r"(a0), "r"(a1), "r"(a2), "r"(a3), "r"(b0), "r"(b1));
}

__device__ __forceinline__ void cp16(unsigned dst, const void* src) {
    asm volatile("cp.async.cg.shared.global [%0], [%1], 16;\n" :: "r"(dst), "l"(src));
}
#define CP_COMMIT() asm volatile("cp.async.commit_group;\n" ::: "memory")
#define CP_WAIT(n)  asm volatile("cp.async.wait_group %0;\n" :: "n"(n) : "memory")

// ---------------------------------------------------------------------------
// Kernel 1: q/k projections, tf32x3 internally; epilogue stores tf32-rounded
// values so fused_attn's E phase needs no conversion at all. (unchanged)
// ---------------------------------------------------------------------------
__global__ __launch_bounds__(256) void qk_gemm_tf32(
    const float* __restrict__ x,
    const float* __restrict__ wq, const float* __restrict__ bq,
    const float* __restrict__ wk, const float* __restrict__ bk)
{
    const int b  = blockIdx.y;
    const int n0 = blockIdx.x * 128;
    const float* Bx = x + (size_t)b * CC * NN;

    __shared__ unsigned Ah[16][72], Al[16][72];
    __shared__ unsigned Bh[16][LDW], Bl[16][LDW];

    const int tid  = threadIdx.x;
    const int wid  = tid >> 5;
    const int lane = tid & 31;
    const int grp  = lane >> 2;
    const int qd   = lane & 3;
    const int wm   = (wid & 1) * 32;
    const int wn   = (wid >> 1) * 32;

    const int arow = tid >> 2;
    const int ak4  = (tid & 3) * 4;
    const float* asrc = (arow < 32) ? (wq + (size_t)arow * CC)
                                    : (wk + (size_t)(arow - 32) * CC);

    float acc[2][4][4];
#pragma unroll
    for (int mi = 0; mi < 2; mi++)
#pragma unroll
        for (int ni = 0; ni < 4; ni++)
#pragma unroll
            for (int r = 0; r < 4; r++) acc[mi][ni][r] = 0.f;

    float4 pa, pb[2];

    pa = *(const float4*)(asrc + ak4);
#pragma unroll
    for (int r = 0; r < 2; r++) {
        int id = tid + r * 256;
        int kb = id >> 5, nb4 = (id & 31) * 4;
        pb[r] = *(const float4*)(Bx + (size_t)kb * NN + n0 + nb4);
    }
    {
        unsigned h0 = f2tf32(pa.x), h1 = f2tf32(pa.y), h2 = f2tf32(pa.z), h3 = f2tf32(pa.w);
        Ah[ak4 + 0][arow] = h0; Al[ak4 + 0][arow] = f2tf32(pa.x - __uint_as_float(h0));
        Ah[ak4 + 1][arow] = h1; Al[ak4 + 1][arow] = f2tf32(pa.y - __uint_as_float(h1));
        Ah[ak4 + 2][arow] = h2; Al[ak4 + 2][arow] = f2tf32(pa.z - __uint_as_float(h2));
        Ah[ak4 + 3][arow] = h3; Al[ak4 + 3][arow] = f2tf32(pa.w - __uint_as_float(h3));
#pragma unroll
        for (int r = 0; r < 2; r++) {
            int id = tid + r * 256;
            int kb = id >> 5, nb4 = (id & 31) * 4;
            uint4 bh, bl;
            bh.x = f2tf32(pb[r].x); bl.x = f2tf32(pb[r].x - __uint_as_float(bh.x));
            bh.y = f2tf32(pb[r].y); bl.y = f2tf32(pb[r].y - __uint_as_float(bh.y));
            bh.z = f2tf32(pb[r].z); bl.z = f2tf32(pb[r].z - __uint_as_float(bh.z));
            bh.w = f2tf32(pb[r].w); bl.w = f2tf32(pb[r].w - __uint_as_float(bh.w));
            *(uint4*)&Bh[kb][nb4] = bh;
            *(uint4*)&Bl[kb][nb4] = bl;
        }
    }
    __syncthreads();

    for (int k0 = 0; k0 < CC; k0 += 16) {
        const bool more = (k0 + 16 < CC);
        if (more) {
            pa = *(const float4*)(asrc + k0 + 16 + ak4);
#pragma unroll
            for (int r = 0; r < 2; r++) {
                int id = tid + r * 256;
                int kb = id >> 5, nb4 = (id & 31) * 4;
                pb[r] = *(const float4*)(Bx + (size_t)(k0 + 16 + kb) * NN + n0 + nb4);
            }
        }
#pragma unroll
        for (int ka = 0; ka < 2; ka++) {
            const int k8 = ka * 8;
            unsigned ah[2][4], al[2][4], bh[4][2], bl[4][2];
#pragma unroll
            for (int mi = 0; mi < 2; mi++) {
                int mr = wm + mi * 16 + grp;
                ah[mi][0] = Ah[k8 + qd][mr];     ah[mi][1] = Ah[k8 + qd][mr + 8];
                ah[mi][2] = Ah[k8 + qd + 4][mr]; ah[mi][3] = Ah[k8 + qd + 4][mr + 8];
                al[mi][0] = Al[k8 + qd][mr];     al[mi][1] = Al[k8 + qd][mr + 8];
                al[mi][2] = Al[k8 + qd + 4][mr]; al[mi][3] = Al[k8 + qd + 4][mr + 8];
            }
#pragma unroll
            for (int ni = 0; ni < 4; ni++) {
                int nc = wn + ni * 8 + grp;
                bh[ni][0] = Bh[k8 + qd][nc]; bh[ni][1] = Bh[k8 + qd + 4][nc];
                bl[ni][0] = Bl[k8 + qd][nc]; bl[ni][1] = Bl[k8 + qd + 4][nc];
            }
#pragma unroll
            for (int mi = 0; mi < 2; mi++)
#pragma unroll
                for (int ni = 0; ni < 4; ni++) {
                    mma_tf32(acc[mi][ni], ah[mi][0], ah[mi][1], ah[mi][2], ah[mi][3],
                             bh[ni][0], bh[ni][1]);
                    mma_tf32(acc[mi][ni], ah[mi][0], ah[mi][1], ah[mi][2], ah[mi][3],
                             bl[ni][0], bl[ni][1]);
                    mma_tf32(acc[mi][ni], al[mi][0], al[mi][1], al[mi][2], al[mi][3],
                             bh[ni][0], bh[ni][1]);
                }
        }
        __syncthreads();
        if (more) {
            unsigned h0 = f2tf32(pa.x), h1 = f2tf32(pa.y), h2 = f2tf32(pa.z), h3 = f2tf32(pa.w);
            Ah[ak4 + 0][arow] = h0; Al[ak4 + 0][arow] = f2tf32(pa.x - __uint_as_float(h0));
            Ah[ak4 + 1][arow] = h1; Al[ak4 + 1][arow] = f2tf32(pa.y - __uint_as_float(h1));
            Ah[ak4 + 2][arow] = h2; Al[ak4 + 2][arow] = f2tf32(pa.z - __uint_as_float(h2));
            Ah[ak4 + 3][arow] = h3; Al[ak4 + 3][arow] = f2tf32(pa.w - __uint_as_float(h3));
#pragma unroll
            for (int r = 0; r < 2; r++) {
                int id = tid + r * 256;
                int kb = id >> 5, nb4 = (id & 31) * 4;
                uint4 bhv, blv;
                bhv.x = f2tf32(pb[r].x); blv.x = f2tf32(pb[r].x - __uint_as_float(bhv.x));
                bhv.y = f2tf32(pb[r].y); blv.y = f2tf32(pb[r].y - __uint_as_float(bhv.y));
                bhv.z = f2tf32(pb[r].z); blv.z = f2tf32(pb[r].z - __uint_as_float(bhv.z));
                bhv.w = f2tf32(pb[r].w); blv.w = f2tf32(pb[r].w - __uint_as_float(bhv.w));
                *(uint4*)&Bh[kb][nb4] = bhv;
                *(uint4*)&Bl[kb][nb4] = blv;
            }
            __syncthreads();
        }
    }

    const float* bias = (wm == 0) ? bq : bk;
    float* op = ((wm == 0) ? g_q : g_kT) + (size_t)b * NN * HH;
#pragma unroll
    for (int mi = 0; mi < 2; mi++) {
        int h0 = mi * 16 + grp;
        int h1 = h0 + 8;
        float b0 = bias[h0];
        float b1 = bias[h1];
#pragma unroll
        for (int ni = 0; ni < 4; ni++) {
            int n = n0 + wn + ni * 8 + qd * 2;
            op[(size_t)n * HH + h0]       = __uint_as_float(f2tf32(acc[mi][ni][0] + b0));
            op[(size_t)(n + 1) * HH + h0] = __uint_as_float(f2tf32(acc[mi][ni][1] + b0));
            op[(size_t)n * HH + h1]       = __uint_as_float(f2tf32(acc[mi][ni][2] + b1));
            op[(size_t)(n + 1) * HH + h1] = __uint_as_float(f2tf32(acc[mi][ni][3] + b1));
        }
    }
}

// ---------------------------------------------------------------------------
// Kernel 2: v = wv @ x + bv  (tf32 MMA), stores tf32-rounded — unchanged.
// ---------------------------------------------------------------------------
__global__ __launch_bounds__(256) void v_gemm_tf32(
    const float* __restrict__ x, const float* __restrict__ wv,
    const float* __restrict__ bv)
{
    const int b  = blockIdx.z;
    const int m0 = blockIdx.y * 128;
    const int n0 = blockIdx.x * 128;
    const float* Bx = x + (size_t)b * CC * NN;

    __shared__ unsigned As[16][LDW];
    __shared__ unsigned Bs[16][LDW];

    const int tid  = threadIdx.x;
    const int wid  = tid >> 5;
    const int lane = tid & 31;
    const int grp  = lane >> 2;
    const int qd   = lane & 3;
    const int wm   = (wid & 1) * 64;
    const int wn   = (wid >> 1) * 32;

    float acc[4][4][4];
#pragma unroll
    for (int mi = 0; mi < 4; mi++)
#pragma unroll
        for (int ni = 0; ni < 4; ni++)
#pragma unroll
            for (int r = 0; r < 4; r++) acc[mi][ni][r] = 0.f;

    float4 pa[2], pb[2];

#pragma unroll
    for (int r = 0; r < 2; r++) {
        int ida = tid + r * 256;
        int mrow = ida >> 2, ka4 = (ida & 3) * 4;
        pa[r] = *(const float4*)(wv + (size_t)(m0 + mrow) * CC + ka4);
        int idb = tid + r * 256;
        int kb = idb >> 5, nb4 = (idb & 31) * 4;
        pb[r] = *(const float4*)(Bx + (size_t)kb * NN + n0 + nb4);
    }
#pragma unroll
    for (int r = 0; r < 2; r++) {
        int ida = tid + r * 256;
        int mrow = ida >> 2, ka4 = (ida & 3) * 4;
        As[ka4 + 0][mrow] = f2tf32(pa[r].x);
        As[ka4 + 1][mrow] = f2tf32(pa[r].y);
        As[ka4 + 2][mrow] = f2tf32(pa[r].z);
        As[ka4 + 3][mrow] = f2tf32(pa[r].w);
        int idb = tid + r * 256;
        int kb = idb >> 5, nb4 = (idb & 31) * 4;
        uint4 bb = make_uint4(f2tf32(pb[r].x), f2tf32(pb[r].y),
                              f2tf32(pb[r].z), f2tf32(pb[r].w));
        *(uint4*)&Bs[kb][nb4] = bb;
    }
    __syncthreads();

    for (int k0 = 0; k0 < CC; k0 += 16) {
        const bool more = (k0 + 16 < CC);
        if (more) {
#pragma unroll
            for (int r = 0; r < 2; r++) {
                int ida = tid + r * 256;
                int mrow = ida >> 2, ka4 = (ida & 3) * 4;
                pa[r] = *(const float4*)(wv + (size_t)(m0 + mrow) * CC + k0 + 16 + ka4);
                int idb = tid + r * 256;
                int kb = idb >> 5, nb4 = (idb & 31) * 4;
                pb[r] = *(const float4*)(Bx + (size_t)(k0 + 16 + kb) * NN + n0 + nb4);
            }
        }
#pragma unroll
        for (int ka = 0; ka < 2; ka++) {
            const int kb8 = ka * 8;
            unsigned af[4][4], bf[4][2];
#pragma unroll
            for (int mi = 0; mi < 4; mi++) {
                int mr = wm + mi * 16 + grp;
                af[mi][0] = As[kb8 + qd][mr];
                af[mi][1] = As[kb8 + qd][mr + 8];
                af[mi][2] = As[kb8 + qd + 4][mr];
                af[mi][3] = As[kb8 + qd + 4][mr + 8];
            }
#pragma unroll
            for (int ni = 0; ni < 4; ni++) {
                int nc = wn + ni * 8 + grp;
                bf[ni][0] = Bs[kb8 + qd][nc];
                bf[ni][1] = Bs[kb8 + qd + 4][nc];
            }
#pragma unroll
            for (int mi = 0; mi < 4; mi++)
#pragma unroll
                for (int ni = 0; ni < 4; ni++)
                    mma_tf32(acc[mi][ni], af[mi][0], af[mi][1], af[mi][2], af[mi][3],
                             bf[ni][0], bf[ni][1]);
        }
        __syncthreads();
        if (more) {
#pragma unroll
            for (int r = 0; r < 2; r++) {
                int ida = tid + r * 256;
                int mrow = ida >> 2, ka4 = (ida & 3) * 4;
                As[ka4 + 0][mrow] = f2tf32(pa[r].x);
                As[ka4 + 1][mrow] = f2tf32(pa[r].y);
                As[ka4 + 2][mrow] = f2tf32(pa[r].z);
                As[ka4 + 3][mrow] = f2tf32(pa[r].w);
                int idb = tid + r * 256;
                int kb = idb >> 5, nb4 = (idb & 31) * 4;
                uint4 bb = make_uint4(f2tf32(pb[r].x), f2tf32(pb[r].y),
                                      f2tf32(pb[r].z), f2tf32(pb[r].w));
                *(uint4*)&Bs[kb][nb4] = bb;
            }
            __syncthreads();
        }
    }

#pragma unroll
    for (int mi = 0; mi < 4; mi++) {
#pragma unroll
        for (int ni = 0; ni < 4; ni++) {
            int row = m0 + wm + mi * 16 + grp;
            int col = n0 + wn + ni * 8 + qd * 2;
            float bias0 = bv[row];
            float bias1 = bv[row + 8];
            float* p0 = g_v + ((size_t)b * CC + row) * NN + col;
            float* p1 = p0 + (size_t)8 * NN;
            float2 o0, o1;
            o0.x = __uint_as_float(f2tf32(acc[mi][ni][0] + bias0));
            o0.y = __uint_as_float(f2tf32(acc[mi][ni][1] + bias0));
            o1.x = __uint_as_float(f2tf32(acc[mi][ni][2] + bias1));
            o1.y = __uint_as_float(f2tf32(acc[mi][ni][3] + bias1));
            *(float2*)p0 = o0;
            *(float2*)p1 = o1;
        }
    }
}

// ---------------------------------------------------------------------------
// PV full-tile: D(c,i) += V(c,j) * P(i,j)^T over the full 64-wide j chunk.
// V stride 68, P stride 68 (both ≡4 mod 32 — conflict-free). 256 MMAs,
// no barriers inside. j order s=0..7 matches the old half0;half1 order, so
// accumulation is bit-identical to round 10.
// ---------------------------------------------------------------------------
__device__ __forceinline__ void pv_tile(const float* sm, float (&pacc)[4][8][4],
                                        int cq, int ih, int grp, int qd, int vb)
{
    const float* vs = sm + OFF_V + vb * (256 * 68) + cq * (64 * 68);
    const float* Ps = sm + OFF_P + ih * (64 * 68);
#pragma unroll
    for (int s = 0; s < 8; s++) {
        unsigned af[4][4];
#pragma unroll
        for (int mi = 0; mi < 4; mi++) {
            af[mi][0] = __float_as_uint(vs[(mi * 16 + grp)     * 68 + 8 * s + qd]);
            af[mi][1] = __float_as_uint(vs[(mi * 16 + grp + 8) * 68 + 8 * s + qd]);
            af[mi][2] = __float_as_uint(vs[(mi * 16 + grp)     * 68 + 8 * s + qd + 4]);
            af[mi][3] = __float_as_uint(vs[(mi * 16 + grp + 8) * 68 + 8 * s + qd + 4]);
        }
        unsigned bf[8][2];
#pragma unroll
        for (int ni = 0; ni < 8; ni++) {
            bf[ni][0] = __float_as_uint(Ps[(ni * 8 + grp) * 68 + 8 * s + qd]);
            bf[ni][1] = __float_as_uint(Ps[(ni * 8 + grp) * 68 + 8 * s + qd + 4]);
        }
#pragma unroll
        for (int mi = 0; mi < 4; mi++)
#pragma unroll
            for (int ni = 0; ni < 8; ni++)
                mma_tf32(pacc[mi][ni], af[mi][0], af[mi][1], af[mi][2], af[mi][3],
                         bf[ni][0], bf[ni][1]);
    }
}

// ---------------------------------------------------------------------------
// Fused: E (tf32 x1) + exp + PV, V+kT full-tile double-buffered, ONE cp group
// and 3 barriers per iteration. grid (16 i-tiles, 8 b), 256 thr, 213KB smem.
// ---------------------------------------------------------------------------
__global__ __launch_bounds__(256, 1) void fused_attn(
    const float* __restrict__ x, float* __restrict__ out)
{
    extern __shared__ float sm[];
    const int b   = blockIdx.y;
    const int i0  = blockIdx.x * 128;
    const int tid = threadIdx.x;
    const int w   = tid >> 5;
    const int lane = tid & 31;
    const int grp = lane >> 2;
    const int qd  = lane & 3;

    const int ei = w & 1, ej = w >> 1;   // E warp tile: (64 i) x (16 j)
    const int cq = w >> 1, ih = w & 1;   // PV warp tile: (64 c) x (64 i)

    unsigned smb = (unsigned)__cvta_generic_to_shared(sm);

    const float* gq = g_q  + ((size_t)b * NN + i0) * HH;
    const float* gk = g_kT + (size_t)b * NN * HH;
    const float* gv = g_v  + (size_t)b * CC * NN;

    // --- prologue group: Q (128x32) + kT(0) + V(0) full tile ---
#pragma unroll
    for (int r = 0; r < 4; r++) {
        int id = tid + 256 * r; int row = id >> 3, ch = id & 7;
        cp16(smb + (OFF_Q + row * 36 + ch * 4) * 4, gq + (size_t)row * HH + ch * 4);
    }
#pragma unroll
    for (int r = 0; r < 2; r++) {
        int id = tid + 256 * r; int row = id >> 3, ch = id & 7;
        cp16(smb + (OFF_KT + row * 36 + ch * 4) * 4, gk + (size_t)row * HH + ch * 4);
    }
#pragma unroll
    for (int r = 0; r < 16; r++) {
        int id = tid + 256 * r; int row = id >> 4, ch = id & 15;
        cp16(smb + (OFF_V + row * 68 + ch * 4) * 4, gv + (size_t)row * NN + ch * 4);
    }
    CP_COMMIT();

    float pacc[4][8][4];
#pragma unroll
    for (int mi = 0; mi < 4; mi++)
#pragma unroll
        for (int ni = 0; ni < 8; ni++)
#pragma unroll
            for (int r = 0; r < 4; r++) pacc[mi][ni][r] = 0.f;
    float rs[8];
#pragma unroll
    for (int k = 0; k < 8; k++) rs[k] = 0.f;

    for (int it = 0; it < NT; it++) {
        const int j0 = it * 64;
        const int kb = it & 1;

        // issue prefetch of iter it+1 (kT + full V) into the other buffers.
        // Target buffers were freed by the final barrier of iter it-1.
        if (it < NT - 1) {
#pragma unroll
            for (int r = 0; r < 2; r++) {
                int id = tid + 256 * r; int row = id >> 3, ch = id & 7;
                cp16(smb + (OFF_KT + (kb ^ 1) * (64 * 36) + row * 36 + ch * 4) * 4,
                     gk + (size_t)(j0 + 64 + row) * HH + ch * 4);
            }
#pragma unroll
            for (int r = 0; r < 16; r++) {
                int id = tid + 256 * r; int row = id >> 4, ch = id & 15;
                cp16(smb + (OFF_V + (kb ^ 1) * (256 * 68) + row * 68 + ch * 4) * 4,
                     gv + (size_t)row * NN + j0 + 64 + ch * 4);
            }
        }
        CP_COMMIT();

        CP_WAIT(1); __syncthreads();   // Q + kT(it) + V(it) ready

        // ---------------- E phase: single tf32 (operands pre-rounded) -------
        float eacc[4][2][4];
#pragma unroll
        for (int mi = 0; mi < 4; mi++)
#pragma unroll
            for (int nj = 0; nj < 2; nj++)
#pragma unroll
                for (int r = 0; r < 4; r++) eacc[mi][nj][r] = 0.f;
        {
            const float* qs = sm + OFF_Q + ei * (64 * 36);
            const float* ks = sm + OFF_KT + kb * (64 * 36) + ej * (16 * 36);
#pragma unroll
            for (int s = 0; s < 4; s++) {
                unsigned af[4][4];
#pragma unroll
                for (int mi = 0; mi < 4; mi++) {
                    int r0 = (mi * 16 + grp)     * 36 + 8 * s + qd;
                    int r1 = (mi * 16 + grp + 8) * 36 + 8 * s + qd;
                    af[mi][0] = __float_as_uint(qs[r0]);
                    af[mi][1] = __float_as_uint(qs[r1]);
                    af[mi][2] = __float_as_uint(qs[r0 + 4]);
                    af[mi][3] = __float_as_uint(qs[r1 + 4]);
                }
                unsigned bf[2][2];
#pragma unroll
                for (int nj = 0; nj < 2; nj++) {
                    bf[nj][0] = __float_as_uint(ks[(nj * 8 + grp) * 36 + 8 * s + qd]);
                    bf[nj][1] = __float_as_uint(ks[(nj * 8 + grp) * 36 + 8 * s + qd + 4]);
                }
#pragma unroll
                for (int mi = 0; mi < 4; mi++)
#pragma unroll
                    for (int nj = 0; nj < 2; nj++)
                        mma_tf32(eacc[mi][nj], af[mi][0], af[mi][1], af[mi][2], af[mi][3],
                                 bf[nj][0], bf[nj][1]);
            }
        }
        // exp -> P (tf32-rounded), accumulate row sums
#pragma unroll
        for (int mi = 0; mi < 4; mi++)
#pragma unroll
            for (int nj = 0; nj < 2; nj++) {
                float e0 = __expf(eacc[mi][nj][0]);
                float e1 = __expf(eacc[mi][nj][1]);
                float e2 = __expf(eacc[mi][nj][2]);
                float e3 = __expf(eacc[mi][nj][3]);
                rs[2 * mi]     += e0 + e1;
                rs[2 * mi + 1] += e2 + e3;
                int row = ei * 64 + mi * 16 + grp;
                int col = ej * 16 + nj * 8 + 2 * qd;
                float2 p0, p1;
                p0.x = __uint_as_float(f2tf32(e0)); p0.y = __uint_as_float(f2tf32(e1));
                p1.x = __uint_as_float(f2tf32(e2)); p1.y = __uint_as_float(f2tf32(e3));
                *(float2*)&sm[OFF_P + row * 68 + col]       = p0;
                *(float2*)&sm[OFF_P + (row + 8) * 68 + col] = p1;
            }
        __syncthreads();               // P visible to all warps

        // ---------------- PV: full 64-j tile, no internal barriers ----------
        pv_tile(sm, pacc, cq, ih, grp, qd, kb);
        __syncthreads();               // V(it)/kT(it)/P free for overwrite
    }

    // ---------------- rowsum reduce + inverse ----------------
#pragma unroll
    for (int k = 0; k < 8; k++) {
        rs[k] += __shfl_xor_sync(0xffffffffu, rs[k], 1);
        rs[k] += __shfl_xor_sync(0xffffffffu, rs[k], 2);
    }
    if (qd == 0) {
#pragma unroll
        for (int mi = 0; mi < 4; mi++) {
            sm[OFF_RS + (ei * 64 + mi * 16 + grp)     * 4 + ej] = rs[2 * mi];
            sm[OFF_RS + (ei * 64 + mi * 16 + grp + 8) * 4 + ej] = rs[2 * mi + 1];
        }
    }
    __syncthreads();
    if (tid < 128) {
        float t = sm[OFF_RS + tid * 4] + sm[OFF_RS + tid * 4 + 1]
                + sm[OFF_RS + tid * 4 + 2] + sm[OFF_RS + tid * 4 + 3];
        sm[OFF_INV + tid] = 1.0f / t;
    }
    __syncthreads();

    // ---------------- epilogue: out = acc/rowsum + x ----------------
#pragma unroll
    for (int mi = 0; mi < 4; mi++) {
        int c = cq * 64 + mi * 16 + grp;
        size_t rb0 = ((size_t)b * CC + c) * NN + i0;
        size_t rb1 = rb0 + (size_t)8 * NN;
#pragma unroll
        for (int ni = 0; ni < 8; ni++) {
            int il = ih * 64 + ni * 8 + 2 * qd;
            float iv0 = sm[OFF_INV + il];
            float iv1 = sm[OFF_INV + il + 1];
            float2 x0 = *(const float2*)(x + rb0 + il);
            float2 x1 = *(const float2*)(x + rb1 + il);
            float2 o0 = make_float2(pacc[mi][ni][0] * iv0 + x0.x,
                                    pacc[mi][ni][1] * iv1 + x0.y);
            float2 o1 = make_float2(pacc[mi][ni][2] * iv0 + x1.x,
                                    pacc[mi][ni][3] * iv1 + x1.y);
            *(float2*)(out + rb0 + il) = o0;
            *(float2*)(out + rb1 + il) = o1;
        }
    }
}

// ---------------------------------------------------------------------------
extern "C" void kernel_launch(void* const* d_in, const int* in_sizes, int n_in,
                              void* d_out, int out_size)
{
    const float* x  = (const float*)d_in[0];
    const float* wq = (const float*)d_in[1];
    const float* bq = (const float*)d_in[2];
    const float* wk = (const float*)d_in[3];
    const float* bk = (const float*)d_in[4];
    const float* wv = (const float*)d_in[5];
    const float* bv = (const float*)d_in[6];
    float* out = (float*)d_out;

    cudaFuncSetAttribute(fused_attn, cudaFuncAttributeMaxDynamicSharedMemorySize,
                         SMEM_BYTES);

    qk_gemm_tf32<<<dim3(NN / 128, BB), 256>>>(x, wq, bq, wk, bk);
    v_gemm_tf32<<<dim3(NN / 128, CC / 128, BB), 256>>>(x, wv, bv);
    fused_attn<<<dim3(NN / 128, BB), 256, SMEM_BYTES>>>(x, out);
}

// round 12
// speedup vs baseline: 1.4866x; 1.4866x over previous
#include <cuda_runtime.h>
#include <cuda_bf16.h>
#include <math.h>

#define BB 8
#define CC 256
#define NN 2048
#define HH 32
#define LDW 136
#define NT 32     // j-iterations: NT * 64 == NN

// Scratch (__device__ globals; no allocation in kernel_launch)
__device__ float    g_q [BB * NN * HH];          // q[b,n,h]   (tf32-rounded)
__device__ float    g_kT[BB * NN * HH];          // k^T[b,n,h] (tf32-rounded)
__device__ unsigned g_v [BB * CC * NN / 2];      // v[b,c,n]   bf16x2 pairs

// fused-kernel smem layout (4-byte word offsets)
#define OFF_Q    0                         // 128 x 36 floats (tf32)
#define OFF_KT   (128*36)                  // 2 x 64 x 36 floats
#define OFF_P    (OFF_KT + 2*64*36)        // 128 x 36 uints (bf16x2 pairs)
#define OFF_V    (OFF_P + 128*36)          // 2 x 256 x 20 uints (bf16x2 pairs)
#define OFF_RS   (OFF_V + 2*256*20)        // 128 x 4 floats
#define OFF_INV  (OFF_RS + 128*4)          // 128 floats
#define SMEM_FLOATS (OFF_INV + 128)
#define SMEM_BYTES  (SMEM_FLOATS * 4)      // 98,816 B

__device__ __forceinline__ unsigned f2tf32(float f) {
    unsigned u;
    asm("cvt.rna.tf32.f32 %0, %1;" : "=r"(u) : "f"(f));
    return u;
}

__device__ __forceinline__ unsigned pack_bf16x2(float lo, float hi) {
    unsigned u;
    asm("cvt.rn.bf16x2.f32 %0, %1, %2;" : "=r"(u) : "f"(hi), "f"(lo));
    return u;
}

__device__ __forceinline__ void mma_tf32(float c[4],
    unsigned a0, unsigned a1, unsigned a2, unsigned a3,
    unsigned b0, unsigned b1)
{
    asm volatile(
        "mma.sync.aligned.m16n8k8.row.col.f32.tf32.tf32.f32 "
        "{%0,%1,%2,%3}, {%4,%5,%6,%7}, {%8,%9}, {%0,%1,%2,%3};"
        : "+f"(c[0]), "+f"(c[1]), "+f"(c[2]), "+f"(c[3])
        : "r"(a0), "r"(a1), "r"(a2), "r"(a3), "r"(b0), "r"(b1));
}

__device__ __forceinline__ void mma_bf16(float c[4],
    unsigned a0, unsigned a1, unsigned a2, unsigned a3,
    unsigned b0, unsigned b1)
{
    asm volatile(
        "mma.sync.aligned.m16n8k16.row.col.f32.bf16.bf16.f32 "
        "{%0,%1,%2,%3}, {%4,%5,%6,%7}, {%8,%9}, {%0,%1,%2,%3};"
        : "+f"(c[0]), "+f"(c[1]), "+f"(c[2]), "+f"(c[3])
        : "r"(a0), "r"(a1), "r"(a2), "r"(a3), "r"(b0), "r"(b1));
}

__device__ __forceinline__ void cp16(unsigned dst, const void* src) {
    asm volatile("cp.async.cg.shared.global [%0], [%1], 16;\n" :: "r"(dst), "l"(src));
}
#define CP_COMMIT() asm volatile("cp.async.commit_group;\n" ::: "memory")
#define CP_WAIT(n)  asm volatile("cp.async.wait_group %0;\n" :: "n"(n) : "memory")

// ---------------------------------------------------------------------------
// Kernel 1: q/k projections, tf32x3 internally; stores tf32-rounded. Unchanged.
// ---------------------------------------------------------------------------
__global__ __launch_bounds__(256) void qk_gemm_tf32(
    const float* __restrict__ x,
    const float* __restrict__ wq, const float* __restrict__ bq,
    const float* __restrict__ wk, const float* __restrict__ bk)
{
    const int b  = blockIdx.y;
    const int n0 = blockIdx.x * 128;
    const float* Bx = x + (size_t)b * CC * NN;

    __shared__ unsigned Ah[16][72], Al[16][72];
    __shared__ unsigned Bh[16][LDW], Bl[16][LDW];

    const int tid  = threadIdx.x;
    const int wid  = tid >> 5;
    const int lane = tid & 31;
    const int grp  = lane >> 2;
    const int qd   = lane & 3;
    const int wm   = (wid & 1) * 32;
    const int wn   = (wid >> 1) * 32;

    const int arow = tid >> 2;
    const int ak4  = (tid & 3) * 4;
    const float* asrc = (arow < 32) ? (wq + (size_t)arow * CC)
                                    : (wk + (size_t)(arow - 32) * CC);

    float acc[2][4][4];
#pragma unroll
    for (int mi = 0; mi < 2; mi++)
#pragma unroll
        for (int ni = 0; ni < 4; ni++)
#pragma unroll
            for (int r = 0; r < 4; r++) acc[mi][ni][r] = 0.f;

    float4 pa, pb[2];

    pa = *(const float4*)(asrc + ak4);
#pragma unroll
    for (int r = 0; r < 2; r++) {
        int id = tid + r * 256;
        int kb = id >> 5, nb4 = (id & 31) * 4;
        pb[r] = *(const float4*)(Bx + (size_t)kb * NN + n0 + nb4);
    }
    {
        unsigned h0 = f2tf32(pa.x), h1 = f2tf32(pa.y), h2 = f2tf32(pa.z), h3 = f2tf32(pa.w);
        Ah[ak4 + 0][arow] = h0; Al[ak4 + 0][arow] = f2tf32(pa.x - __uint_as_float(h0));
        Ah[ak4 + 1][arow] = h1; Al[ak4 + 1][arow] = f2tf32(pa.y - __uint_as_float(h1));
        Ah[ak4 + 2][arow] = h2; Al[ak4 + 2][arow] = f2tf32(pa.z - __uint_as_float(h2));
        Ah[ak4 + 3][arow] = h3; Al[ak4 + 3][arow] = f2tf32(pa.w - __uint_as_float(h3));
#pragma unroll
        for (int r = 0; r < 2; r++) {
            int id = tid + r * 256;
            int kb = id >> 5, nb4 = (id & 31) * 4;
            uint4 bh, bl;
            bh.x = f2tf32(pb[r].x); bl.x = f2tf32(pb[r].x - __uint_as_float(bh.x));
            bh.y = f2tf32(pb[r].y); bl.y = f2tf32(pb[r].y - __uint_as_float(bh.y));
            bh.z = f2tf32(pb[r].z); bl.z = f2tf32(pb[r].z - __uint_as_float(bh.z));
            bh.w = f2tf32(pb[r].w); bl.w = f2tf32(pb[r].w - __uint_as_float(bh.w));
            *(uint4*)&Bh[kb][nb4] = bh;
            *(uint4*)&Bl[kb][nb4] = bl;
        }
    }
    __syncthreads();

    for (int k0 = 0; k0 < CC; k0 += 16) {
        const bool more = (k0 + 16 < CC);
        if (more) {
            pa = *(const float4*)(asrc + k0 + 16 + ak4);
#pragma unroll
            for (int r = 0; r < 2; r++) {
                int id = tid + r * 256;
                int kb = id >> 5, nb4 = (id & 31) * 4;
                pb[r] = *(const float4*)(Bx + (size_t)(k0 + 16 + kb) * NN + n0 + nb4);
            }
        }
#pragma unroll
        for (int ka = 0; ka < 2; ka++) {
            const int k8 = ka * 8;
            unsigned ah[2][4], al[2][4], bh[4][2], bl[4][2];
#pragma unroll
            for (int mi = 0; mi < 2; mi++) {
                int mr = wm + mi * 16 + grp;
                ah[mi][0] = Ah[k8 + qd][mr];     ah[mi][1] = Ah[k8 + qd][mr + 8];
                ah[mi][2] = Ah[k8 + qd + 4][mr]; ah[mi][3] = Ah[k8 + qd + 4][mr + 8];
                al[mi][0] = Al[k8 + qd][mr];     al[mi][1] = Al[k8 + qd][mr + 8];
                al[mi][2] = Al[k8 + qd + 4][mr]; al[mi][3] = Al[k8 + qd + 4][mr + 8];
            }
#pragma unroll
            for (int ni = 0; ni < 4; ni++) {
                int nc = wn + ni * 8 + grp;
                bh[ni][0] = Bh[k8 + qd][nc]; bh[ni][1] = Bh[k8 + qd + 4][nc];
                bl[ni][0] = Bl[k8 + qd][nc]; bl[ni][1] = Bl[k8 + qd + 4][nc];
            }
#pragma unroll
            for (int mi = 0; mi < 2; mi++)
#pragma unroll
                for (int ni = 0; ni < 4; ni++) {
                    mma_tf32(acc[mi][ni], ah[mi][0], ah[mi][1], ah[mi][2], ah[mi][3],
                             bh[ni][0], bh[ni][1]);
                    mma_tf32(acc[mi][ni], ah[mi][0], ah[mi][1], ah[mi][2], ah[mi][3],
                             bl[ni][0], bl[ni][1]);
                    mma_tf32(acc[mi][ni], al[mi][0], al[mi][1], al[mi][2], al[mi][3],
                             bh[ni][0], bh[ni][1]);
                }
        }
        __syncthreads();
        if (more) {
            unsigned h0 = f2tf32(pa.x), h1 = f2tf32(pa.y), h2 = f2tf32(pa.z), h3 = f2tf32(pa.w);
            Ah[ak4 + 0][arow] = h0; Al[ak4 + 0][arow] = f2tf32(pa.x - __uint_as_float(h0));
            Ah[ak4 + 1][arow] = h1; Al[ak4 + 1][arow] = f2tf32(pa.y - __uint_as_float(h1));
            Ah[ak4 + 2][arow] = h2; Al[ak4 + 2][arow] = f2tf32(pa.z - __uint_as_float(h2));
            Ah[ak4 + 3][arow] = h3; Al[ak4 + 3][arow] = f2tf32(pa.w - __uint_as_float(h3));
#pragma unroll
            for (int r = 0; r < 2; r++) {
                int id = tid + r * 256;
                int kb = id >> 5, nb4 = (id & 31) * 4;
                uint4 bhv, blv;
                bhv.x = f2tf32(pb[r].x); blv.x = f2tf32(pb[r].x - __uint_as_float(bhv.x));
                bhv.y = f2tf32(pb[r].y); blv.y = f2tf32(pb[r].y - __uint_as_float(bhv.y));
                bhv.z = f2tf32(pb[r].z); blv.z = f2tf32(pb[r].z - __uint_as_float(bhv.z));
                bhv.w = f2tf32(pb[r].w); blv.w = f2tf32(pb[r].w - __uint_as_float(bhv.w));
                *(uint4*)&Bh[kb][nb4] = bhv;
                *(uint4*)&Bl[kb][nb4] = blv;
            }
            __syncthreads();
        }
    }

    const float* bias = (wm == 0) ? bq : bk;
    float* op = ((wm == 0) ? g_q : g_kT) + (size_t)b * NN * HH;
#pragma unroll
    for (int mi = 0; mi < 2; mi++) {
        int h0 = mi * 16 + grp;
        int h1 = h0 + 8;
        float b0 = bias[h0];
        float b1 = bias[h1];
#pragma unroll
        for (int ni = 0; ni < 4; ni++) {
            int n = n0 + wn + ni * 8 + qd * 2;
            op[(size_t)n * HH + h0]       = __uint_as_float(f2tf32(acc[mi][ni][0] + b0));
            op[(size_t)(n + 1) * HH + h0] = __uint_as_float(f2tf32(acc[mi][ni][1] + b0));
            op[(size_t)n * HH + h1]       = __uint_as_float(f2tf32(acc[mi][ni][2] + b1));
            op[(size_t)(n + 1) * HH + h1] = __uint_as_float(f2tf32(acc[mi][ni][3] + b1));
        }
    }
}

// ---------------------------------------------------------------------------
// Kernel 2: v = wv @ x + bv  (tf32 MMA); epilogue stores bf16x2 pairs.
// ---------------------------------------------------------------------------
__global__ __launch_bounds__(256) void v_gemm_tf32(
    const float* __restrict__ x, const float* __restrict__ wv,
    const float* __restrict__ bv)
{
    const int b  = blockIdx.z;
    const int m0 = blockIdx.y * 128;
    const int n0 = blockIdx.x * 128;
    const float* Bx = x + (size_t)b * CC * NN;

    __shared__ unsigned As[16][LDW];
    __shared__ unsigned Bs[16][LDW];

    const int tid  = threadIdx.x;
    const int wid  = tid >> 5;
    const int lane = tid & 31;
    const int grp  = lane >> 2;
    const int qd   = lane & 3;
    const int wm   = (wid & 1) * 64;
    const int wn   = (wid >> 1) * 32;

    float acc[4][4][4];
#pragma unroll
    for (int mi = 0; mi < 4; mi++)
#pragma unroll
        for (int ni = 0; ni < 4; ni++)
#pragma unroll
            for (int r = 0; r < 4; r++) acc[mi][ni][r] = 0.f;

    float4 pa[2], pb[2];

#pragma unroll
    for (int r = 0; r < 2; r++) {
        int ida = tid + r * 256;
        int mrow = ida >> 2, ka4 = (ida & 3) * 4;
        pa[r] = *(const float4*)(wv + (size_t)(m0 + mrow) * CC + ka4);
        int idb = tid + r * 256;
        int kb = idb >> 5, nb4 = (idb & 31) * 4;
        pb[r] = *(const float4*)(Bx + (size_t)kb * NN + n0 + nb4);
    }
#pragma unroll
    for (int r = 0; r < 2; r++) {
        int ida = tid + r * 256;
        int mrow = ida >> 2, ka4 = (ida & 3) * 4;
        As[ka4 + 0][mrow] = f2tf32(pa[r].x);
        As[ka4 + 1][mrow] = f2tf32(pa[r].y);
        As[ka4 + 2][mrow] = f2tf32(pa[r].z);
        As[ka4 + 3][mrow] = f2tf32(pa[r].w);
        int idb = tid + r * 256;
        int kb = idb >> 5, nb4 = (idb & 31) * 4;
        uint4 bb = make_uint4(f2tf32(pb[r].x), f2tf32(pb[r].y),
                              f2tf32(pb[r].z), f2tf32(pb[r].w));
        *(uint4*)&Bs[kb][nb4] = bb;
    }
    __syncthreads();

    for (int k0 = 0; k0 < CC; k0 += 16) {
        const bool more = (k0 + 16 < CC);
        if (more) {
#pragma unroll
            for (int r = 0; r < 2; r++) {
                int ida = tid + r * 256;
                int mrow = ida >> 2, ka4 = (ida & 3) * 4;
                pa[r] = *(const float4*)(wv + (size_t)(m0 + mrow) * CC + k0 + 16 + ka4);
                int idb = tid + r * 256;
                int kb = idb >> 5, nb4 = (idb & 31) * 4;
                pb[r] = *(const float4*)(Bx + (size_t)(k0 + 16 + kb) * NN + n0 + nb4);
            }
        }
#pragma unroll
        for (int ka = 0; ka < 2; ka++) {
            const int kb8 = ka * 8;
            unsigned af[4][4], bf[4][2];
#pragma unroll
            for (int mi = 0; mi < 4; mi++) {
                int mr = wm + mi * 16 + grp;
                af[mi][0] = As[kb8 + qd][mr];
                af[mi][1] = As[kb8 + qd][mr + 8];
                af[mi][2] = As[kb8 + qd + 4][mr];
                af[mi][3] = As[kb8 + qd + 4][mr + 8];
            }
#pragma unroll
            for (int ni = 0; ni < 4; ni++) {
                int nc = wn + ni * 8 + grp;
                bf[ni][0] = Bs[kb8 + qd][nc];
                bf[ni][1] = Bs[kb8 + qd + 4][nc];
            }
#pragma unroll
            for (int mi = 0; mi < 4; mi++)
#pragma unroll
                for (int ni = 0; ni < 4; ni++)
                    mma_tf32(acc[mi][ni], af[mi][0], af[mi][1], af[mi][2], af[mi][3],
                             bf[ni][0], bf[ni][1]);
        }
        __syncthreads();
        if (more) {
#pragma unroll
            for (int r = 0; r < 2; r++) {
                int ida = tid + r * 256;
                int mrow = ida >> 2, ka4 = (ida & 3) * 4;
                As[ka4 + 0][mrow] = f2tf32(pa[r].x);
                As[ka4 + 1][mrow] = f2tf32(pa[r].y);
                As[ka4 + 2][mrow] = f2tf32(pa[r].z);
                As[ka4 + 3][mrow] = f2tf32(pa[r].w);
                int idb = tid + r * 256;
                int kb = idb >> 5, nb4 = (idb & 31) * 4;
                uint4 bb = make_uint4(f2tf32(pb[r].x), f2tf32(pb[r].y),
                                      f2tf32(pb[r].z), f2tf32(pb[r].w));
                *(uint4*)&Bs[kb][nb4] = bb;
            }
            __syncthreads();
        }
    }

    // epilogue: bf16x2 pairs into g_v
#pragma unroll
    for (int mi = 0; mi < 4; mi++) {
#pragma unroll
        for (int ni = 0; ni < 4; ni++) {
            int row = m0 + wm + mi * 16 + grp;
            int col = n0 + wn + ni * 8 + qd * 2;
            float bias0 = bv[row];
            float bias1 = bv[row + 8];
            unsigned* p0 = g_v + ((size_t)b * CC + row) * (NN / 2) + col / 2;
            unsigned* p1 = p0 + (size_t)8 * (NN / 2);
            *p0 = pack_bf16x2(acc[mi][ni][0] + bias0, acc[mi][ni][1] + bias0);
            *p1 = pack_bf16x2(acc[mi][ni][2] + bias1, acc[mi][ni][3] + bias1);
        }
    }
}

// ---------------------------------------------------------------------------
// PV inner (bf16 m16n8k16): D(c,i) += V(c,j)*P(i,j)^T over one 32-j half.
// V half-buffer: uint pairs [256][20]; P: uint pairs [128][36].
// 2 k-chunks of 16 -> 64 MMAs per call (was 128 tf32).
// ---------------------------------------------------------------------------
__device__ __forceinline__ void pv_half(const float* sm, float (&pacc)[4][8][4],
                                        int cq, int ih, int grp, int qd, int h)
{
    const unsigned* Vp = (const unsigned*)(sm + OFF_V) + h * (256 * 20) + (cq * 64) * 20;
    const unsigned* Pp = (const unsigned*)(sm + OFF_P) + (ih * 64) * 36 + h * 16;
#pragma unroll
    for (int s = 0; s < 2; s++) {
        const int bp = 8 * s;
        unsigned af[4][4];
#pragma unroll
        for (int mi = 0; mi < 4; mi++) {
            af[mi][0] = Vp[(mi * 16 + grp)     * 20 + bp + qd];
            af[mi][1] = Vp[(mi * 16 + grp + 8) * 20 + bp + qd];
            af[mi][2] = Vp[(mi * 16 + grp)     * 20 + bp + qd + 4];
            af[mi][3] = Vp[(mi * 16 + grp + 8) * 20 + bp + qd + 4];
        }
        unsigned bf[8][2];
#pragma unroll
        for (int ni = 0; ni < 8; ni++) {
            bf[ni][0] = Pp[(ni * 8 + grp) * 36 + bp + qd];
            bf[ni][1] = Pp[(ni * 8 + grp) * 36 + bp + qd + 4];
        }
#pragma unroll
        for (int mi = 0; mi < 4; mi++)
#pragma unroll
            for (int ni = 0; ni < 8; ni++)
                mma_bf16(pacc[mi][ni], af[mi][0], af[mi][1], af[mi][2], af[mi][3],
                         bf[ni][0], bf[ni][1]);
    }
}

// ---------------------------------------------------------------------------
// Fused: E (tf32 x1) + exp + PV (bf16). R10 skeleton (proven), bf16 V/P.
// grid (16 i-tiles, 8 batches), 256 threads, 98.8KB smem.
// ---------------------------------------------------------------------------
__global__ __launch_bounds__(256, 1) void fused_attn(
    const float* __restrict__ x, float* __restrict__ out)
{
    extern __shared__ float sm[];
    const int b   = blockIdx.y;
    const int i0  = blockIdx.x * 128;
    const int tid = threadIdx.x;
    const int w   = tid >> 5;
    const int lane = tid & 31;
    const int grp = lane >> 2;
    const int qd  = lane & 3;

    const int ei = w & 1, ej = w >> 1;   // E warp tile: (64 i) x (16 j)
    const int cq = w >> 1, ih = w & 1;   // PV warp tile: (64 c) x (64 i)

    unsigned smb = (unsigned)__cvta_generic_to_shared(sm);

    const float*    gq = g_q  + ((size_t)b * NN + i0) * HH;
    const float*    gk = g_kT + (size_t)b * NN * HH;
    const unsigned* gv = g_v  + (size_t)b * CC * (NN / 2);

    // --- group A: q tile (128x32) + kT tile 0 (64x32) ---
#pragma unroll
    for (int r = 0; r < 4; r++) {
        int id = tid + 256 * r; int row = id >> 3, ch = id & 7;
        cp16(smb + (OFF_Q + row * 36 + ch * 4) * 4, gq + (size_t)row * HH + ch * 4);
    }
#pragma unroll
    for (int r = 0; r < 2; r++) {
        int id = tid + 256 * r; int row = id >> 3, ch = id & 7;
        cp16(smb + (OFF_KT + row * 36 + ch * 4) * 4, gk + (size_t)row * HH + ch * 4);
    }
    CP_COMMIT();
    // --- group B: v half0 of iter 0 (256 rows x 16 pairs) ---
#pragma unroll
    for (int r = 0; r < 4; r++) {
        int id = tid + 256 * r; int row = id >> 2, ch = id & 3;
        cp16(smb + (OFF_V + row * 20 + ch * 4) * 4, gv + (size_t)row * (NN / 2) + ch * 4);
    }
    CP_COMMIT();

    float pacc[4][8][4];
#pragma unroll
    for (int mi = 0; mi < 4; mi++)
#pragma unroll
        for (int ni = 0; ni < 8; ni++)
#pragma unroll
            for (int r = 0; r < 4; r++) pacc[mi][ni][r] = 0.f;
    float rs[8];
#pragma unroll
    for (int k = 0; k < 8; k++) rs[k] = 0.f;

    for (int it = 0; it < NT; it++) {
        const int jp0 = it * 32;       // pair offset of this iter's 64-j chunk
        const int kb = it & 1;

        // C1: v half1 of this iter -> vbuf1
#pragma unroll
        for (int r = 0; r < 4; r++) {
            int id = tid + 256 * r; int row = id >> 2, ch = id & 3;
            cp16(smb + (OFF_V + 256 * 20 + row * 20 + ch * 4) * 4,
                 gv + (size_t)row * (NN / 2) + jp0 + 16 + ch * 4);
        }
        CP_COMMIT();
        // C2: kT(it+1) -> other kT buffer
        if (it < NT - 1) {
#pragma unroll
            for (int r = 0; r < 2; r++) {
                int id = tid + 256 * r; int row = id >> 3, ch = id & 7;
                cp16(smb + (OFF_KT + (kb ^ 1) * (64 * 36) + row * 36 + ch * 4) * 4,
                     gk + (size_t)(it * 64 + 64 + row) * HH + ch * 4);
            }
        }
        CP_COMMIT();

        CP_WAIT(3); __syncthreads();   // q + kT(it) ready

        // ---------------- E phase: single tf32 (operands pre-rounded) -------
        float eacc[4][2][4];
#pragma unroll
        for (int mi = 0; mi < 4; mi++)
#pragma unroll
            for (int nj = 0; nj < 2; nj++)
#pragma unroll
                for (int r = 0; r < 4; r++) eacc[mi][nj][r] = 0.f;
        {
            const float* qs = sm + OFF_Q + ei * (64 * 36);
            const float* ks = sm + OFF_KT + kb * (64 * 36) + ej * (16 * 36);
#pragma unroll
            for (int s = 0; s < 4; s++) {
                unsigned af[4][4];
#pragma unroll
                for (int mi = 0; mi < 4; mi++) {
                    int r0 = (mi * 16 + grp)     * 36 + 8 * s + qd;
                    int r1 = (mi * 16 + grp + 8) * 36 + 8 * s + qd;
                    af[mi][0] = __float_as_uint(qs[r0]);
                    af[mi][1] = __float_as_uint(qs[r1]);
                    af[mi][2] = __float_as_uint(qs[r0 + 4]);
                    af[mi][3] = __float_as_uint(qs[r1 + 4]);
                }
                unsigned bf[2][2];
#pragma unroll
                for (int nj = 0; nj < 2; nj++) {
                    bf[nj][0] = __float_as_uint(ks[(nj * 8 + grp) * 36 + 8 * s + qd]);
                    bf[nj][1] = __float_as_uint(ks[(nj * 8 + grp) * 36 + 8 * s + qd + 4]);
                }
#pragma unroll
                for (int mi = 0; mi < 4; mi++)
#pragma unroll
                    for (int nj = 0; nj < 2; nj++)
                        mma_tf32(eacc[mi][nj], af[mi][0], af[mi][1], af[mi][2], af[mi][3],
                                 bf[nj][0], bf[nj][1]);
            }
        }
        // exp -> P (bf16x2 pairs), accumulate row sums (fp32)
        {
            unsigned* Pp = (unsigned*)(sm + OFF_P);
#pragma unroll
            for (int mi = 0; mi < 4; mi++)
#pragma unroll
                for (int nj = 0; nj < 2; nj++) {
                    float e0 = __expf(eacc[mi][nj][0]);
                    float e1 = __expf(eacc[mi][nj][1]);
                    float e2 = __expf(eacc[mi][nj][2]);
                    float e3 = __expf(eacc[mi][nj][3]);
                    rs[2 * mi]     += e0 + e1;
                    rs[2 * mi + 1] += e2 + e3;
                    int row = ei * 64 + mi * 16 + grp;
                    int pcol = ej * 8 + nj * 4 + qd;      // pair index within 32
                    Pp[row * 36 + pcol]       = pack_bf16x2(e0, e1);
                    Pp[(row + 8) * 36 + pcol] = pack_bf16x2(e2, e3);
                }
        }

        // ---------------- PV half 0 ----------------
        CP_WAIT(2); __syncthreads();   // P visible + v half0 ready
        pv_half(sm, pacc, cq, ih, grp, qd, 0);
        __syncthreads();               // all warps done with vbuf0
        // C3: v half0 of next iter -> vbuf0
        if (it < NT - 1) {
#pragma unroll
            for (int r = 0; r < 4; r++) {
                int id = tid + 256 * r; int row = id >> 2, ch = id & 3;
                cp16(smb + (OFF_V + row * 20 + ch * 4) * 4,
                     gv + (size_t)row * (NN / 2) + jp0 + 32 + ch * 4);
            }
        }
        CP_COMMIT();

        // ---------------- PV half 1 ----------------
        CP_WAIT(2); __syncthreads();   // v half1 ready
        pv_half(sm, pacc, cq, ih, grp, qd, 1);
        __syncthreads();               // vbuf1 + P free for next iter
    }

    // ---------------- rowsum reduce + inverse ----------------
#pragma unroll
    for (int k = 0; k < 8; k++) {
        rs[k] += __shfl_xor_sync(0xffffffffu, rs[k], 1);
        rs[k] += __shfl_xor_sync(0xffffffffu, rs[k], 2);
    }
    if (qd == 0) {
#pragma unroll
        for (int mi = 0; mi < 4; mi++) {
            sm[OFF_RS + (ei * 64 + mi * 16 + grp)     * 4 + ej] = rs[2 * mi];
            sm[OFF_RS + (ei * 64 + mi * 16 + grp + 8) * 4 + ej] = rs[2 * mi + 1];
        }
    }
    __syncthreads();
    if (tid < 128) {
        float t = sm[OFF_RS + tid * 4] + sm[OFF_RS + tid * 4 + 1]
                + sm[OFF_RS + tid * 4 + 2] + sm[OFF_RS + tid * 4 + 3];
        sm[OFF_INV + tid] = 1.0f / t;
    }
    __syncthreads();

    // ---------------- epilogue: out = acc/rowsum + x ----------------
#pragma unroll
    for (int mi = 0; mi < 4; mi++) {
        int c = cq * 64 + mi * 16 + grp;
        size_t rb0 = ((size_t)b * CC + c) * NN + i0;
        size_t rb1 = rb0 + (size_t)8 * NN;
#pragma unroll
        for (int ni = 0; ni < 8; ni++) {
            int il = ih * 64 + ni * 8 + 2 * qd;
            float iv0 = sm[OFF_INV + il];
            float iv1 = sm[OFF_INV + il + 1];
            float2 x0 = *(const float2*)(x + rb0 + il);
            float2 x1 = *(const float2*)(x + rb1 + il);
            float2 o0 = make_float2(pacc[mi][ni][0] * iv0 + x0.x,
                                    pacc[mi][ni][1] * iv1 + x0.y);
            float2 o1 = make_float2(pacc[mi][ni][2] * iv0 + x1.x,
                                    pacc[mi][ni][3] * iv1 + x1.y);
            *(float2*)(out + rb0 + il) = o0;
            *(float2*)(out + rb1 + il) = o1;
        }
    }
}

// ---------------------------------------------------------------------------
extern "C" void kernel_launch(void* const* d_in, const int* in_sizes, int n_in,
                              void* d_out, int out_size)
{
    const float* x  = (const float*)d_in[0];
    const float* wq = (const float*)d_in[1];
    const float* bq = (const float*)d_in[2];
    const float* wk = (const float*)d_in[3];
    const float* bk = (const float*)d_in[4];
    const float* wv = (const float*)d_in[5];
    const float* bv = (const float*)d_in[6];
    float* out = (float*)d_out;

    cudaFuncSetAttribute(fused_attn, cudaFuncAttributeMaxDynamicSharedMemorySize,
                         SMEM_BYTES);

    qk_gemm_tf32<<<dim3(NN / 128, BB), 256>>>(x, wq, bq, wk, bk);
    v_gemm_tf32<<<dim3(NN / 128, CC / 128, BB), 256>>>(x, wv, bv);
    fused_attn<<<dim3(NN / 128, BB), 256, SMEM_BYTES>>>(x, out);
}